// round 8
// baseline (speedup 1.0000x reference)
#include <cuda_runtime.h>

// Spalize: out[k][c][h][w] = img[c][h][w] * (mask[h][w] == k), k in [0,50),
// plus the mask appended (as float) if out_size covers it.
//
// 8 pixels/thread, 256-bit stores (STG.256). Split output:
//   k <  25 (78MB): st.global.L2::evict_last.v8.b32 -> candidate-resident L2
//                   set that should survive the streaming sweep and write-hit
//                   across graph replays.
//   k >= 25 + tail: __stcs float4 streaming (evict-first).

#define KCH 50
#define CCH 3
#define KSPLIT 10
#define KCHUNK (KCH / KSPLIT)   // 5
#define PERSIST_CHUNKS 5        // ks<5 => k in [0,25)

__device__ __forceinline__ int detect_is64(const int* __restrict__ mask) {
    const int lane = threadIdx.x & 31;
    const int w1 = __ldg(&mask[2 * lane + 1]);
    const int w2 = __ldg(&mask[2 * (lane + 32) + 1]);
    const unsigned b = __ballot_sync(0xffffffffu, (w1 | w2) == 0);
    return b == 0xffffffffu;
}

// Load 8 mask labels for pixel block t (pixels t*8 .. t*8+7)
__device__ __forceinline__ void load_mask8(const int* __restrict__ mask,
                                           int t, int is64, int m[8]) {
    if (is64) {
        const int base = t * 16;  // 8 int64s = 16 words, low word at even idx
        #pragma unroll
        for (int i = 0; i < 8; i++) m[i] = mask[base + 2 * i];
    } else {
        const int4 a = reinterpret_cast<const int4*>(mask)[2 * t];
        const int4 b = reinterpret_cast<const int4*>(mask)[2 * t + 1];
        m[0] = a.x; m[1] = a.y; m[2] = a.z; m[3] = a.w;
        m[4] = b.x; m[5] = b.y; m[6] = b.z; m[7] = b.w;
    }
}

__device__ __forceinline__ void st_evict_last8(float* p, const float v[8]) {
    asm volatile(
        "st.global.L2::evict_last.v8.b32 [%0], {%1,%2,%3,%4,%5,%6,%7,%8};"
        :: "l"(p),
           "r"(__float_as_uint(v[0])), "r"(__float_as_uint(v[1])),
           "r"(__float_as_uint(v[2])), "r"(__float_as_uint(v[3])),
           "r"(__float_as_uint(v[4])), "r"(__float_as_uint(v[5])),
           "r"(__float_as_uint(v[6])), "r"(__float_as_uint(v[7]))
        : "memory");
}

__device__ __forceinline__ void st_cs8(float* p, const float v[8]) {
    float4 a = make_float4(v[0], v[1], v[2], v[3]);
    float4 b = make_float4(v[4], v[5], v[6], v[7]);
    __stcs(reinterpret_cast<float4*>(p), a);
    __stcs(reinterpret_cast<float4*>(p) + 1, b);
}

__global__ void __launch_bounds__(256) spalize_fused_kernel(
    const float* __restrict__ img,
    const int*   __restrict__ mask,
    float*       __restrict__ out,
    int nq8,           // HW/8
    int nblocksQ,      // nq8/256
    int nSpalBlocks)   // nblocksQ * KSPLIT
{
    const int is64 = detect_is64(mask);
    const int HW = nq8 * 8;

    if (blockIdx.x >= nSpalBlocks) {
        // ---- mask tail: out[n_img + i] = (float)mask[i], 8 per thread ----
        const int tb = blockIdx.x - nSpalBlocks;
        const int t  = tb * blockDim.x + threadIdx.x;
        if (t < nq8) {
            int m[8];
            load_mask8(mask, t, is64, m);
            float v[8];
            #pragma unroll
            for (int i = 0; i < 8; i++) v[i] = (float)m[i];
            const long long n_img = (long long)KCH * CCH * HW;
            st_cs8(out + n_img + (long long)t * 8, v);
        }
        return;
    }

    // ---- spalize: 8 contiguous pixels per thread ----
    const int qb = blockIdx.x % nblocksQ;
    const int ks = blockIdx.x / nblocksQ;
    const int t  = qb * blockDim.x + threadIdx.x;
    if (t >= nq8) return;

    int m[8];
    load_mask8(mask, t, is64, m);

    // img pixels for 3 channels
    float pix[3][8];
    const float4* img4 = reinterpret_cast<const float4*>(img);
    const int nq4 = nq8 * 2;  // HW/4
    #pragma unroll
    for (int c = 0; c < CCH; c++) {
        float4 a = img4[c * nq4 + 2 * t];
        float4 b = img4[c * nq4 + 2 * t + 1];
        pix[c][0] = a.x; pix[c][1] = a.y; pix[c][2] = a.z; pix[c][3] = a.w;
        pix[c][4] = b.x; pix[c][5] = b.y; pix[c][6] = b.z; pix[c][7] = b.w;
    }

    const int k0 = ks * KCHUNK;
    const long long tOff = (long long)t * 8;

    #pragma unroll
    for (int kk = 0; kk < KCHUNK; kk++) {
        const int k = k0 + kk;
        #pragma unroll
        for (int c = 0; c < CCH; c++) {
            float v[8];
            #pragma unroll
            for (int i = 0; i < 8; i++)
                v[i] = (m[i] == k) ? pix[c][i] : 0.0f;
            float* dst = out + ((long long)(k * CCH + c) * HW + tOff);
            if (ks < PERSIST_CHUNKS) st_evict_last8(dst, v);
            else                     st_cs8(dst, v);
        }
    }
}

extern "C" void kernel_launch(void* const* d_in, const int* in_sizes, int n_in,
                              void* d_out, int out_size)
{
    const float* img  = (const float*)d_in[0];
    const int*   mask = (const int*)d_in[1];
    float*       out  = (float*)d_out;

    const int HW  = in_sizes[0] / CCH;      // 512*512
    const int nq8 = HW >> 3;                // 32768

    const int threads     = 256;
    const int nblocksQ    = (nq8 + threads - 1) / threads;  // 128
    const int nSpalBlocks = nblocksQ * KSPLIT;              // 1280

    const long long n_img = (long long)KCH * CCH * HW;
    const bool wantTail = ((long long)out_size >= n_img + HW);
    const int grid = nSpalBlocks + (wantTail ? nblocksQ : 0);

    spalize_fused_kernel<<<grid, threads>>>(img, mask, out, nq8, nblocksQ, nSpalBlocks);
}

// round 9
// speedup vs baseline: 1.3613x; 1.3613x over previous
#include <cuda_runtime.h>

// Spalize: out[k][c][h][w] = img[c][h][w] * (mask[h][w] == k), k in [0,50),
// plus the mask appended (as float) if out_size covers it.
//
// R5 base (1 quad/thread, fully coalesced float4, uniform __stcs streaming
// stores) + single delta: KSPLIT 10 -> 25 (KCHUNK 5 -> 2). Grid goes
// 2816 -> 6656 blocks (~45/SM) for finer wave balance and more concurrent
// independent store streams. Inputs are L2-resident, so the extra 2.5x
// input re-reads are absorbed by L2 headroom.

#define KCH 50
#define CCH 3
#define KSPLIT 25
#define KCHUNK (KCH / KSPLIT)   // 2

__device__ __forceinline__ int detect_is64(const int* __restrict__ mask) {
    const int lane = threadIdx.x & 31;
    const int w1 = __ldg(&mask[2 * lane + 1]);
    const int w2 = __ldg(&mask[2 * (lane + 32) + 1]);
    const unsigned b = __ballot_sync(0xffffffffu, (w1 | w2) == 0);
    return b == 0xffffffffu;
}

__device__ __forceinline__ void load_mask_quad(const int* __restrict__ mask,
                                               int q, int is64,
                                               int& m0, int& m1, int& m2, int& m3) {
    if (is64) {
        const int base = q * 8;   // 4 int64s; low word at even idx
        m0 = mask[base + 0]; m1 = mask[base + 2];
        m2 = mask[base + 4]; m3 = mask[base + 6];
    } else {
        const int4 mm = reinterpret_cast<const int4*>(mask)[q];
        m0 = mm.x; m1 = mm.y; m2 = mm.z; m3 = mm.w;
    }
}

__device__ __forceinline__ float4 sel4(float4 ic, int m0, int m1, int m2, int m3, int k) {
    float4 v;
    v.x = (m0 == k) ? ic.x : 0.0f;
    v.y = (m1 == k) ? ic.y : 0.0f;
    v.z = (m2 == k) ? ic.z : 0.0f;
    v.w = (m3 == k) ? ic.w : 0.0f;
    return v;
}

__global__ void __launch_bounds__(256) spalize_fused_kernel(
    const float* __restrict__ img,
    const int*   __restrict__ mask,
    float*       __restrict__ out,
    int nq,            // HW/4
    int nblocksQ,      // ceil(nq/256)
    int nSpalBlocks)   // nblocksQ * KSPLIT
{
    const int is64 = detect_is64(mask);

    if (blockIdx.x >= nSpalBlocks) {
        // ---- mask tail: out[n_img + i] = (float)mask[i], 4 per thread ----
        const int tb = blockIdx.x - nSpalBlocks;
        const int q  = tb * blockDim.x + threadIdx.x;
        if (q < nq) {
            int m0, m1, m2, m3;
            load_mask_quad(mask, q, is64, m0, m1, m2, m3);
            float4 v = make_float4((float)m0, (float)m1, (float)m2, (float)m3);
            const long long n_img4 = (long long)KCH * CCH * nq;  // float4 units
            __stcs(&reinterpret_cast<float4*>(out)[n_img4 + q], v);
        }
        return;
    }

    // ---- spalize: 1 quad per thread, lanes contiguous ----
    const int qb = blockIdx.x % nblocksQ;
    const int ks = blockIdx.x / nblocksQ;
    const int q  = qb * blockDim.x + threadIdx.x;
    if (q >= nq) return;

    int m0, m1, m2, m3;
    load_mask_quad(mask, q, is64, m0, m1, m2, m3);

    const float4* img4 = reinterpret_cast<const float4*>(img);
    float4 ic0 = img4[0 * nq + q];
    float4 ic1 = img4[1 * nq + q];
    float4 ic2 = img4[2 * nq + q];

    float4* out4 = reinterpret_cast<float4*>(out);
    const int k0 = ks * KCHUNK;

    #pragma unroll
    for (int kk = 0; kk < KCHUNK; kk++) {
        const int k = k0 + kk;
        const long long obase = (long long)(k * CCH) * nq + q;
        __stcs(&out4[obase + 0LL * nq], sel4(ic0, m0, m1, m2, m3, k));
        __stcs(&out4[obase + 1LL * nq], sel4(ic1, m0, m1, m2, m3, k));
        __stcs(&out4[obase + 2LL * nq], sel4(ic2, m0, m1, m2, m3, k));
    }
}

extern "C" void kernel_launch(void* const* d_in, const int* in_sizes, int n_in,
                              void* d_out, int out_size)
{
    const float* img  = (const float*)d_in[0];
    const int*   mask = (const int*)d_in[1];
    float*       out  = (float*)d_out;

    const int HW = in_sizes[0] / CCH;       // 512*512
    const int nq = HW >> 2;                 // 65536

    const int threads     = 256;
    const int nblocksQ    = (nq + threads - 1) / threads;   // 256
    const int nSpalBlocks = nblocksQ * KSPLIT;              // 6400

    const long long n_img = (long long)KCH * CCH * HW;
    const bool wantTail = ((long long)out_size >= n_img + HW);
    const int grid = nSpalBlocks + (wantTail ? nblocksQ : 0);

    spalize_fused_kernel<<<grid, threads>>>(img, mask, out, nq, nblocksQ, nSpalBlocks);
}